// round 11
// baseline (speedup 1.0000x reference)
#include <cuda_runtime.h>
#include <cuda_fp16.h>
#include <mma.h>
using namespace nvcuda;

#define HD 128
#define MAXN 100096
#define MAXE 1600000
#define SK 136   // smem stride in halves (padded)
#define CAP 128  // fixed CSR bucket capacity per node (max degree ~45 for this data)

// ---------------- device scratch (static, no allocation) ----------------
__device__ __align__(16) __half g_bufH[MAXN * HD];  // GEMM output (fp16, gathered by agg)
__device__ __align__(16) __half g_bufB[MAXN * HD];  // aggregation output (fp16 activations)
__device__ __align__(16) __half g_W1h[HD * HD];     // fp16 weights (pre-converted)
__device__ __align__(16) __half g_W2h[HD * HD];
__device__ int g_cnt[MAXN];          // per-dst degree (atomic)
__device__ int g_csr[MAXN * CAP];    // fixed-stride buckets of src indices

// ---------------- W fp32 -> fp16 pre-conversion (once per launch) ----------------
__global__ void convert_w_kernel(const float* __restrict__ W1,
                                 const float* __restrict__ W2) {
    int i = blockIdx.x * blockDim.x + threadIdx.x;   // 8192 float2 per matrix
    if (i < HD * HD / 2) {
        float2 v = ((const float2*)W1)[i];
        ((__half2*)g_W1h)[i] = __floats2half2_rn(v.x, v.y);
        float2 u = ((const float2*)W2)[i];
        ((__half2*)g_W2h)[i] = __floats2half2_rn(u.x, u.y);
    }
}

// ---------------- single-pass CSR build ----------------
__global__ void build_csr_kernel(const int* __restrict__ adj, int E_) {
    int e = blockIdx.x * blockDim.x + threadIdx.x;
    if (e < E_) {
        int s = adj[e];
        int d = adj[E_ + e];
        int slot = atomicAdd(&g_cnt[d], 1);
        if (slot < CAP) g_csr[d * CAP + slot] = s;
    }
}

// ---------------- tensor-core GEMM (R6/R10 body; W now fp16) ----------------
// C[r] = fp16( (A[r] @ W + b) * norm[r] ),  norm[r] = rsqrt(cnt[r]) (0 if cnt==0)
// 256 threads, 128-row tile, K=128 resident, HMMA fp16-in/fp32-accum.
template<bool AHALF>
__global__ void gemm_mma_kernel(const void* __restrict__ Ain,
                                const __half* __restrict__ Wh,
                                const float* __restrict__ bias,
                                __half* __restrict__ C, int n) {
    extern __shared__ char smem_raw[];
    __half* As = (__half*)smem_raw;           // 128 x SK halves
    __half* Ws = As + 128 * SK;               // 128 x SK halves
    float* stage = (float*)smem_raw;          // reused after mma loop
    int tid = threadIdx.x;
    int row0 = blockIdx.x * 128;

    // W fp16 -> smem (2048 uint4, 8 per thread)
    {
        const uint4* W4 = (const uint4*)Wh;
        #pragma unroll
        for (int i = tid; i < 128 * 16; i += 256) {
            int r = i >> 4, c8 = i & 15;
            *(uint4*)(Ws + r * SK + c8 * 8) = W4[i];
        }
    }
    // A tile -> fp16 smem
    if (AHALF) {
        const uint4* A4 = (const uint4*)Ain;   // 8 halves per uint4, 16 per row
        #pragma unroll
        for (int i = tid; i < 128 * 16; i += 256) {
            int r = i >> 4, c8 = i & 15;
            int gr = row0 + r;
            uint4 v = (gr < n) ? A4[gr * 16 + c8] : make_uint4(0, 0, 0, 0);
            *(uint4*)(As + r * SK + c8 * 8) = v;
        }
    } else {
        const float4* A4 = (const float4*)Ain;
        #pragma unroll
        for (int i = tid; i < 128 * 32; i += 256) {
            int r = i >> 5, c4 = i & 31;
            int gr = row0 + r;
            float4 v = (gr < n) ? A4[gr * 32 + c4] : make_float4(0.f, 0.f, 0.f, 0.f);
            __half2* d = (__half2*)(As + r * SK + c4 * 4);
            d[0] = __floats2half2_rn(v.x, v.y);
            d[1] = __floats2half2_rn(v.z, v.w);
        }
    }
    __syncthreads();

    int w = tid >> 5;
    int lane = tid & 31;
    int wm = (w >> 1) * 32;     // warp row base
    int wn = (w & 1) * 64;      // warp col base

    wmma::fragment<wmma::accumulator, 16, 16, 16, float> acc[2][4];
    #pragma unroll
    for (int p = 0; p < 2; p++)
        #pragma unroll
        for (int q = 0; q < 4; q++) wmma::fill_fragment(acc[p][q], 0.0f);

    #pragma unroll
    for (int k = 0; k < 128; k += 16) {
        wmma::fragment<wmma::matrix_a, 16, 16, 16, __half, wmma::row_major> af[2];
        wmma::fragment<wmma::matrix_b, 16, 16, 16, __half, wmma::row_major> bf[4];
        #pragma unroll
        for (int p = 0; p < 2; p++)
            wmma::load_matrix_sync(af[p], As + (wm + 16 * p) * SK + k, SK);
        #pragma unroll
        for (int q = 0; q < 4; q++)
            wmma::load_matrix_sync(bf[q], Ws + k * SK + wn + 16 * q, SK);
        #pragma unroll
        for (int p = 0; p < 2; p++)
            #pragma unroll
            for (int q = 0; q < 4; q++)
                wmma::mma_sync(acc[p][q], af[p], bf[q], acc[p][q]);
    }
    __syncthreads();   // all warps done reading As/Ws before staging overwrites

    float* st = stage + w * (32 * 72);
    #pragma unroll
    for (int p = 0; p < 2; p++)
        #pragma unroll
        for (int q = 0; q < 4; q++)
            wmma::store_matrix_sync(st + 16 * p * 72 + 16 * q, acc[p][q], 72,
                                    wmma::mem_row_major);
    __syncwarp();

    // epilogue: (v + bias) * norm[row] -> fp16
    float2 bb = ((const float2*)bias)[(wn >> 1) + lane];
    __half2* C2 = (__half2*)C;
    #pragma unroll
    for (int r = 0; r < 32; r++) {
        int gr = row0 + wm + r;
        if (gr < n) {
            int c = g_cnt[gr];
            float nr = (c > 0) ? rsqrtf((float)c) : 0.0f;
            float2 v = *(float2*)(st + r * 72 + lane * 2);
            C2[gr * 64 + (wn >> 1) + lane] =
                __floats2half2_rn((v.x + bb.x) * nr, (v.y + bb.y) * nr);
        }
    }
}

// ---- aggregation (R10 verbatim): pairwise HADD2 + fp32 accumulation ----
__global__ void aggregate_kernel(const __half* __restrict__ Hs,
                                 __half* __restrict__ Out, int n) {
    int gw = (blockIdx.x * blockDim.x + threadIdx.x) >> 5;
    int lane = threadIdx.x & 31;
    if (gw >= n) return;
    int cnt_true = g_cnt[gw];
    int cnt = cnt_true < CAP ? cnt_true : CAP;
    const int* bucket = g_csr + gw * CAP;
    const uint2* H2 = (const uint2*)Hs;   // row stride = 32 uint2 (256B)
    float ax = 0.f, ay = 0.f, az = 0.f, aw = 0.f;
    for (int base = 0; base < cnt; base += 32) {
        int rem = cnt - base;
        int e = 0;
        if (lane < rem) e = bucket[base + lane];
        int m = rem < 32 ? rem : 32;
        int jm = m & ~1;
        for (int j = 0; j < jm; j += 2) {
            int s0 = __shfl_sync(0xffffffffu, e, j);
            int s1 = __shfl_sync(0xffffffffu, e, j + 1);
            uint2 v0 = __ldg(&H2[s0 * 32 + lane]);
            uint2 v1 = __ldg(&H2[s1 * 32 + lane]);
            __half2 p0 = __hadd2(*(__half2*)&v0.x, *(__half2*)&v1.x);
            __half2 p1 = __hadd2(*(__half2*)&v0.y, *(__half2*)&v1.y);
            float2 f0 = __half22float2(p0);
            float2 f1 = __half22float2(p1);
            ax += f0.x; ay += f0.y; az += f1.x; aw += f1.y;
        }
        if (m & 1) {
            int s = __shfl_sync(0xffffffffu, e, m - 1);
            uint2 v = __ldg(&H2[s * 32 + lane]);
            float2 f0 = __half22float2(*(__half2*)&v.x);
            float2 f1 = __half22float2(*(__half2*)&v.y);
            ax += f0.x; ay += f0.y; az += f1.x; aw += f1.y;
        }
    }
    float nr = (cnt_true > 0) ? rsqrtf((float)cnt_true) : 0.0f;
    __half2 o0 = __floats2half2_rn(fmaxf(ax * nr, 0.f), fmaxf(ay * nr, 0.f));
    __half2 o1 = __floats2half2_rn(fmaxf(az * nr, 0.f), fmaxf(aw * nr, 0.f));
    uint2 o;
    o.x = *(unsigned*)&o0;
    o.y = *(unsigned*)&o1;
    ((uint2*)Out)[gw * 32 + lane] = o;
}

// ---------------- pooling + MLP head (one block per graph) ----------------
__device__ __forceinline__ int lower_bound_dev(const int* a, int n, int key) {
    int lo = 0, hi = n;
    while (lo < hi) {
        int mid = (lo + hi) >> 1;
        if (a[mid] < key) lo = mid + 1; else hi = mid;
    }
    return lo;
}

__global__ void pool_head_kernel(const __half* __restrict__ H,
                                 const int* __restrict__ gidx,
                                 const float* __restrict__ Wfc,
                                 const float* __restrict__ bfc,
                                 const float* __restrict__ Wout,
                                 const float* __restrict__ bout,
                                 float* __restrict__ out, int n) {
    __shared__ float gf[HD];
    __shared__ float red[HD];
    __shared__ int bounds[2];
    int g = blockIdx.x, t = threadIdx.x;
    if (t < 2) bounds[t] = lower_bound_dev(gidx, n, g + t);
    __syncthreads();
    int start = bounds[0], end = bounds[1];
    float s = 0.f;
    for (int i = start; i < end; i++) s += __half2float(H[i * HD + t]);
    gf[t] = s / fmaxf((float)(end - start), 1.0f);
    __syncthreads();
    float acc = bfc[t];
    #pragma unroll 8
    for (int k = 0; k < HD; k++) acc += gf[k] * Wfc[k * HD + t];
    red[t] = fmaxf(acc, 0.f) * Wout[t];
    __syncthreads();
    #pragma unroll
    for (int sft = 64; sft > 0; sft >>= 1) {
        if (t < sft) red[t] += red[t + sft];
        __syncthreads();
    }
    if (t == 0) out[g] = red[0] + bout[0];
}

// ---------------- launch ----------------
extern "C" void kernel_launch(void* const* d_in, const int* in_sizes, int n_in,
                              void* d_out, int out_size) {
    const float* node = (const float*)d_in[0];
    const int*   adj  = (const int*)d_in[1];
    const int*   gidx = (const int*)d_in[2];
    // d_in[3] = is_training (ignored, eval mode)
    const float* W1   = (const float*)d_in[4];
    const float* b1   = (const float*)d_in[5];
    const float* W2   = (const float*)d_in[6];
    const float* b2   = (const float*)d_in[7];
    const float* Wfc  = (const float*)d_in[8];
    const float* bfc  = (const float*)d_in[9];
    const float* Wout = (const float*)d_in[10];
    const float* bout = (const float*)d_in[11];

    int n  = in_sizes[2];          // N nodes
    int E_ = in_sizes[1] / 2;      // E edges
    int G_ = out_size;             // G graphs (OUT=1)

    __half* bufH; __half* bufB; __half* w1h; __half* w2h; int* cntPtr;
    cudaGetSymbolAddress((void**)&bufH, g_bufH);
    cudaGetSymbolAddress((void**)&bufB, g_bufB);
    cudaGetSymbolAddress((void**)&w1h, g_W1h);
    cudaGetSymbolAddress((void**)&w2h, g_W2h);
    cudaGetSymbolAddress((void**)&cntPtr, g_cnt);

    // smem: max(two 128xSK half tiles, 8 warps * 32*72 floats staging)
    const int gemm_smem = (2 * 128 * SK * 2 > 8 * 32 * 72 * 4)
                              ? 2 * 128 * SK * 2 : 8 * 32 * 72 * 4;
    cudaFuncSetAttribute(gemm_mma_kernel<false>,
                         cudaFuncAttributeMaxDynamicSharedMemorySize, gemm_smem);
    cudaFuncSetAttribute(gemm_mma_kernel<true>,
                         cudaFuncAttributeMaxDynamicSharedMemorySize, gemm_smem);

    int gemm_blocks = (n + 127) / 128;
    int agg_blocks  = (n + 7) / 8;   // 8 warps / block, 1 warp per node

    // prep: zero degree counters, fp16 weights, bucket CSR build
    cudaMemsetAsync(cntPtr, 0, (size_t)MAXN * sizeof(int));
    convert_w_kernel<<<(HD * HD / 2 + 255) / 256, 256>>>(W1, W2);
    build_csr_kernel<<<(E_ + 255) / 256, 256>>>(adj, E_);

    // layer 1
    gemm_mma_kernel<false><<<gemm_blocks, 256, gemm_smem>>>(node, w1h, b1, bufH, n);
    aggregate_kernel<<<agg_blocks, 256>>>(bufH, bufB, n);
    // layer 2
    gemm_mma_kernel<true><<<gemm_blocks, 256, gemm_smem>>>(bufB, w2h, b2, bufH, n);
    aggregate_kernel<<<agg_blocks, 256>>>(bufH, bufB, n);
    // pool + head
    pool_head_kernel<<<G_, HD>>>(bufB, gidx, Wfc, bfc, Wout, bout,
                                 (float*)d_out, n);
}

// round 12
// speedup vs baseline: 1.0768x; 1.0768x over previous
#include <cuda_runtime.h>
#include <cuda_fp16.h>
#include <mma.h>
using namespace nvcuda;

#define HD 128
#define MAXN 100096
#define MAXE 1600000
#define SK 136   // smem stride in halves (padded)
#define CAP 128  // fixed CSR bucket capacity per node (max degree ~45 for this data)

// ---------------- device scratch (static, no allocation) ----------------
__device__ __align__(16) __half g_bufH[MAXN * HD];  // GEMM output (fp16, gathered by agg)
__device__ __align__(16) __half g_bufB[MAXN * HD];  // aggregation output (fp16 activations)
__device__ int g_cnt[MAXN];          // per-dst degree (atomic)
__device__ int g_csr[MAXN * CAP];    // fixed-stride buckets of src indices

// ---------------- single-pass CSR build ----------------
__global__ void build_csr_kernel(const int* __restrict__ adj, int E_) {
    int e = blockIdx.x * blockDim.x + threadIdx.x;
    if (e < E_) {
        int s = adj[e];
        int d = adj[E_ + e];
        int slot = atomicAdd(&g_cnt[d], 1);
        if (slot < CAP) g_csr[d * CAP + slot] = s;
    }
}

// ---------------- tensor-core GEMM (R6/R10 version, verbatim) ----------------
// C[r] = fp16( (A[r] @ W + b) * norm[r] ),  norm[r] = rsqrt(cnt[r]) (0 if cnt==0)
// 256 threads, 128-row tile, K=128 resident, HMMA fp16-in/fp32-accum.
template<bool AHALF>
__global__ void gemm_mma_kernel(const void* __restrict__ Ain,
                                const float* __restrict__ W,
                                const float* __restrict__ bias,
                                __half* __restrict__ C, int n) {
    extern __shared__ char smem_raw[];
    __half* As = (__half*)smem_raw;           // 128 x SK halves
    __half* Ws = As + 128 * SK;               // 128 x SK halves
    float* stage = (float*)smem_raw;          // reused after mma loop
    int tid = threadIdx.x;
    int row0 = blockIdx.x * 128;

    // W fp32 -> fp16 smem
    {
        const float4* W4 = (const float4*)W;
        #pragma unroll
        for (int i = tid; i < 128 * 32; i += 256) {
            int r = i >> 5, c4 = i & 31;
            float4 v = W4[i];
            __half2* d = (__half2*)(Ws + r * SK + c4 * 4);
            d[0] = __floats2half2_rn(v.x, v.y);
            d[1] = __floats2half2_rn(v.z, v.w);
        }
    }
    // A tile -> fp16 smem
    if (AHALF) {
        const uint4* A4 = (const uint4*)Ain;   // 8 halves per uint4, 16 per row
        #pragma unroll
        for (int i = tid; i < 128 * 16; i += 256) {
            int r = i >> 4, c8 = i & 15;
            int gr = row0 + r;
            uint4 v = (gr < n) ? A4[gr * 16 + c8] : make_uint4(0, 0, 0, 0);
            *(uint4*)(As + r * SK + c8 * 8) = v;
        }
    } else {
        const float4* A4 = (const float4*)Ain;
        #pragma unroll
        for (int i = tid; i < 128 * 32; i += 256) {
            int r = i >> 5, c4 = i & 31;
            int gr = row0 + r;
            float4 v = (gr < n) ? A4[gr * 32 + c4] : make_float4(0.f, 0.f, 0.f, 0.f);
            __half2* d = (__half2*)(As + r * SK + c4 * 4);
            d[0] = __floats2half2_rn(v.x, v.y);
            d[1] = __floats2half2_rn(v.z, v.w);
        }
    }
    __syncthreads();

    int w = tid >> 5;
    int lane = tid & 31;
    int wm = (w >> 1) * 32;     // warp row base
    int wn = (w & 1) * 64;      // warp col base

    wmma::fragment<wmma::accumulator, 16, 16, 16, float> acc[2][4];
    #pragma unroll
    for (int p = 0; p < 2; p++)
        #pragma unroll
        for (int q = 0; q < 4; q++) wmma::fill_fragment(acc[p][q], 0.0f);

    #pragma unroll
    for (int k = 0; k < 128; k += 16) {
        wmma::fragment<wmma::matrix_a, 16, 16, 16, __half, wmma::row_major> af[2];
        wmma::fragment<wmma::matrix_b, 16, 16, 16, __half, wmma::row_major> bf[4];
        #pragma unroll
        for (int p = 0; p < 2; p++)
            wmma::load_matrix_sync(af[p], As + (wm + 16 * p) * SK + k, SK);
        #pragma unroll
        for (int q = 0; q < 4; q++)
            wmma::load_matrix_sync(bf[q], Ws + k * SK + wn + 16 * q, SK);
        #pragma unroll
        for (int p = 0; p < 2; p++)
            #pragma unroll
            for (int q = 0; q < 4; q++)
                wmma::mma_sync(acc[p][q], af[p], bf[q], acc[p][q]);
    }
    __syncthreads();   // all warps done reading As/Ws before staging overwrites

    float* st = stage + w * (32 * 72);
    #pragma unroll
    for (int p = 0; p < 2; p++)
        #pragma unroll
        for (int q = 0; q < 4; q++)
            wmma::store_matrix_sync(st + 16 * p * 72 + 16 * q, acc[p][q], 72,
                                    wmma::mem_row_major);
    __syncwarp();

    // epilogue: (v + bias) * norm[row] -> fp16
    float2 bb = ((const float2*)bias)[(wn >> 1) + lane];
    __half2* C2 = (__half2*)C;
    #pragma unroll
    for (int r = 0; r < 32; r++) {
        int gr = row0 + wm + r;
        if (gr < n) {
            int c = g_cnt[gr];
            float nr = (c > 0) ? rsqrtf((float)c) : 0.0f;
            float2 v = *(float2*)(st + r * 72 + lane * 2);
            C2[gr * 64 + (wn >> 1) + lane] =
                __floats2half2_rn((v.x + bb.x) * nr, (v.y + bb.y) * nr);
        }
    }
}

// ---- aggregation: Out[d] = fp16( relu(norm[d] * sum_{src in bucket(d)} Hs[src]) ) ----
// one warp per dst node; lane l owns 4 halves (8B) of the 256B fp16 row.
// QUAD inner step: 4 independent LDGs in flight, two-level fp16 pairwise adds,
// one convert per 4 edges; fp32 accumulation above.
__global__ void aggregate_kernel(const __half* __restrict__ Hs,
                                 __half* __restrict__ Out, int n) {
    int gw = (blockIdx.x * blockDim.x + threadIdx.x) >> 5;
    int lane = threadIdx.x & 31;
    if (gw >= n) return;
    int cnt_true = g_cnt[gw];
    int cnt = cnt_true < CAP ? cnt_true : CAP;
    const int* bucket = g_csr + gw * CAP;
    const uint2* H2 = (const uint2*)Hs;   // row stride = 32 uint2 (256B)
    float ax = 0.f, ay = 0.f, az = 0.f, aw = 0.f;
    for (int base = 0; base < cnt; base += 32) {
        int rem = cnt - base;
        int e = 0;
        if (lane < rem) e = bucket[base + lane];
        int m = rem < 32 ? rem : 32;
        int j = 0;
        for (; j + 4 <= m; j += 4) {
            int s0 = __shfl_sync(0xffffffffu, e, j);
            int s1 = __shfl_sync(0xffffffffu, e, j + 1);
            int s2 = __shfl_sync(0xffffffffu, e, j + 2);
            int s3 = __shfl_sync(0xffffffffu, e, j + 3);
            uint2 v0 = __ldg(&H2[s0 * 32 + lane]);
            uint2 v1 = __ldg(&H2[s1 * 32 + lane]);
            uint2 v2 = __ldg(&H2[s2 * 32 + lane]);
            uint2 v3 = __ldg(&H2[s3 * 32 + lane]);
            __half2 p0 = __hadd2(*(__half2*)&v0.x, *(__half2*)&v1.x);
            __half2 p1 = __hadd2(*(__half2*)&v0.y, *(__half2*)&v1.y);
            __half2 q0 = __hadd2(*(__half2*)&v2.x, *(__half2*)&v3.x);
            __half2 q1 = __hadd2(*(__half2*)&v2.y, *(__half2*)&v3.y);
            __half2 r0 = __hadd2(p0, q0);
            __half2 r1 = __hadd2(p1, q1);
            float2 f0 = __half22float2(r0);
            float2 f1 = __half22float2(r1);
            ax += f0.x; ay += f0.y; az += f1.x; aw += f1.y;
        }
        if (j + 2 <= m) {
            int s0 = __shfl_sync(0xffffffffu, e, j);
            int s1 = __shfl_sync(0xffffffffu, e, j + 1);
            uint2 v0 = __ldg(&H2[s0 * 32 + lane]);
            uint2 v1 = __ldg(&H2[s1 * 32 + lane]);
            __half2 p0 = __hadd2(*(__half2*)&v0.x, *(__half2*)&v1.x);
            __half2 p1 = __hadd2(*(__half2*)&v0.y, *(__half2*)&v1.y);
            float2 f0 = __half22float2(p0);
            float2 f1 = __half22float2(p1);
            ax += f0.x; ay += f0.y; az += f1.x; aw += f1.y;
            j += 2;
        }
        if (j < m) {
            int s = __shfl_sync(0xffffffffu, e, j);
            uint2 v = __ldg(&H2[s * 32 + lane]);
            float2 f0 = __half22float2(*(__half2*)&v.x);
            float2 f1 = __half22float2(*(__half2*)&v.y);
            ax += f0.x; ay += f0.y; az += f1.x; aw += f1.y;
        }
    }
    float nr = (cnt_true > 0) ? rsqrtf((float)cnt_true) : 0.0f;
    __half2 o0 = __floats2half2_rn(fmaxf(ax * nr, 0.f), fmaxf(ay * nr, 0.f));
    __half2 o1 = __floats2half2_rn(fmaxf(az * nr, 0.f), fmaxf(aw * nr, 0.f));
    uint2 o;
    o.x = *(unsigned*)&o0;
    o.y = *(unsigned*)&o1;
    ((uint2*)Out)[gw * 32 + lane] = o;
}

// ---------------- pooling + MLP head (one block per graph) ----------------
__device__ __forceinline__ int lower_bound_dev(const int* a, int n, int key) {
    int lo = 0, hi = n;
    while (lo < hi) {
        int mid = (lo + hi) >> 1;
        if (a[mid] < key) lo = mid + 1; else hi = mid;
    }
    return lo;
}

__global__ void pool_head_kernel(const __half* __restrict__ H,
                                 const int* __restrict__ gidx,
                                 const float* __restrict__ Wfc,
                                 const float* __restrict__ bfc,
                                 const float* __restrict__ Wout,
                                 const float* __restrict__ bout,
                                 float* __restrict__ out, int n) {
    __shared__ float gf[HD];
    __shared__ float red[HD];
    __shared__ int bounds[2];
    int g = blockIdx.x, t = threadIdx.x;
    if (t < 2) bounds[t] = lower_bound_dev(gidx, n, g + t);
    __syncthreads();
    int start = bounds[0], end = bounds[1];
    float s = 0.f;
    for (int i = start; i < end; i++) s += __half2float(H[i * HD + t]);
    gf[t] = s / fmaxf((float)(end - start), 1.0f);
    __syncthreads();
    float acc = bfc[t];
    #pragma unroll 8
    for (int k = 0; k < HD; k++) acc += gf[k] * Wfc[k * HD + t];
    red[t] = fmaxf(acc, 0.f) * Wout[t];
    __syncthreads();
    #pragma unroll
    for (int sft = 64; sft > 0; sft >>= 1) {
        if (t < sft) red[t] += red[t + sft];
        __syncthreads();
    }
    if (t == 0) out[g] = red[0] + bout[0];
}

// ---------------- launch ----------------
extern "C" void kernel_launch(void* const* d_in, const int* in_sizes, int n_in,
                              void* d_out, int out_size) {
    const float* node = (const float*)d_in[0];
    const int*   adj  = (const int*)d_in[1];
    const int*   gidx = (const int*)d_in[2];
    // d_in[3] = is_training (ignored, eval mode)
    const float* W1   = (const float*)d_in[4];
    const float* b1   = (const float*)d_in[5];
    const float* W2   = (const float*)d_in[6];
    const float* b2   = (const float*)d_in[7];
    const float* Wfc  = (const float*)d_in[8];
    const float* bfc  = (const float*)d_in[9];
    const float* Wout = (const float*)d_in[10];
    const float* bout = (const float*)d_in[11];

    int n  = in_sizes[2];          // N nodes
    int E_ = in_sizes[1] / 2;      // E edges
    int G_ = out_size;             // G graphs (OUT=1)

    __half* bufH; __half* bufB; int* cntPtr;
    cudaGetSymbolAddress((void**)&bufH, g_bufH);
    cudaGetSymbolAddress((void**)&bufB, g_bufB);
    cudaGetSymbolAddress((void**)&cntPtr, g_cnt);

    // smem: max(two 128xSK half tiles, 8 warps * 32*72 floats staging)
    const int gemm_smem = (2 * 128 * SK * 2 > 8 * 32 * 72 * 4)
                              ? 2 * 128 * SK * 2 : 8 * 32 * 72 * 4;
    cudaFuncSetAttribute(gemm_mma_kernel<false>,
                         cudaFuncAttributeMaxDynamicSharedMemorySize, gemm_smem);
    cudaFuncSetAttribute(gemm_mma_kernel<true>,
                         cudaFuncAttributeMaxDynamicSharedMemorySize, gemm_smem);

    int gemm_blocks = (n + 127) / 128;
    int agg_blocks  = (n + 7) / 8;   // 8 warps / block, 1 warp per node

    // single-pass CSR build (degrees + fixed-stride buckets)
    cudaMemsetAsync(cntPtr, 0, (size_t)MAXN * sizeof(int));
    build_csr_kernel<<<(E_ + 255) / 256, 256>>>(adj, E_);

    // layer 1
    gemm_mma_kernel<false><<<gemm_blocks, 256, gemm_smem>>>(node, W1, b1, bufH, n);
    aggregate_kernel<<<agg_blocks, 256>>>(bufH, bufB, n);
    // layer 2
    gemm_mma_kernel<true><<<gemm_blocks, 256, gemm_smem>>>(bufB, W2, b2, bufH, n);
    aggregate_kernel<<<agg_blocks, 256>>>(bufH, bufB, n);
    // pool + head
    pool_head_kernel<<<G_, HD>>>(bufB, gidx, Wfc, bfc, Wout, bout,
                                 (float*)d_out, n);
}